// round 7
// baseline (speedup 1.0000x reference)
#include <cuda_runtime.h>
#include <math.h>

// Problem constants (fixed by the reference)
#define NN    10000
#define EE    160000
#define CC    16
#define CHW   1024       // C*H*W
#define DE    64         // edge feature dim
#define HID   128        // hidden dim
#define NSEG  (2 * NN)   // (node, dir) segments; dir 0 = out (r<c), 1 = in (r>c)
#define NSCANB ((NSEG + 1023) / 1024)   // 20 scan blocks

// ---------------------------------------------------------------------------
// Scratch (__device__ globals; no allocations allowed)
// ---------------------------------------------------------------------------
__device__ float g_sum_in [NN];
__device__ float g_sum_out[NN];
__device__ float g_exp[EE];
__device__ int   g_row[EE];
__device__ int   g_col[EE];
__device__ int   g_is64;
__device__ int   g_cnt[NSEG];
__device__ int   g_off[NSEG + 1];
__device__ int   g_pos[NSEG];
__device__ int   g_bsum[NSCANB];
__device__ int   g_scol[EE];       // col of sorted edge
__device__ float g_sw  [EE];       // softmax weight of sorted edge

// ---------------------------------------------------------------------------
// f32x2 packed helpers (sm_100+): 2 fp32 FMAs per issue slot.
// ---------------------------------------------------------------------------
__device__ __forceinline__ unsigned long long ffma2(unsigned long long a,
                                                    unsigned long long b,
                                                    unsigned long long c) {
    unsigned long long d;
    asm("fma.rn.f32x2 %0, %1, %2, %3;" : "=l"(d) : "l"(a), "l"(b), "l"(c));
    return d;
}
__device__ __forceinline__ unsigned long long pack2(float a) {
    unsigned long long r;
    unsigned int u = __float_as_uint(a);
    asm("mov.b64 %0, {%1, %1};" : "=l"(r) : "r"(u));
    return r;
}
union U64F2 { unsigned long long u; float2 f; };

// ---------------------------------------------------------------------------
// Kernel 1: zero accumulators + (block 0) detect int64 vs int32 edge_index.
// ---------------------------------------------------------------------------
__global__ void zero_kernel(const int* __restrict__ v32) {
    int i = blockIdx.x * blockDim.x + threadIdx.x;
    if (i < NSEG) g_cnt[i] = 0;
    if (i < NN) { g_sum_in[i] = 0.f; g_sum_out[i] = 0.f; }
    if (blockIdx.x == 0 && threadIdx.x < 32) {
        int t = threadIdx.x;
        int nz = 0;
#pragma unroll
        for (int q = 0; q < 4; q++)
            nz |= (v32[2 * (t + q * 32) + 1] != 0);
#pragma unroll
        for (int s = 16; s > 0; s >>= 1)
            nz |= __shfl_xor_sync(0xffffffffu, nz, s);
        if (t == 0) g_is64 = nz ? 0 : 1;
    }
}

// ---------------------------------------------------------------------------
// Kernel 2: decode edge_index + segment histogram (merged)
// ---------------------------------------------------------------------------
__global__ void decode_kernel(const int* __restrict__ v32) {
    int e = blockIdx.x * blockDim.x + threadIdx.x;
    if (e >= EE) return;
    int r, c;
    if (g_is64) { r = v32[2 * e]; c = v32[2 * (EE + e)]; }
    else        { r = v32[e];     c = v32[EE + e]; }
    g_row[e] = r;
    g_col[e] = c;
    if (r != c) atomicAdd(&g_cnt[r * 2 + ((r < c) ? 0 : 1)], 1);
}

// ---------------------------------------------------------------------------
// Kernel 3a: per-block local scan + block sums
// ---------------------------------------------------------------------------
__global__ void scanA_kernel() {      // NSCANB blocks x 1024
    __shared__ int wsum[32];
    const int t = threadIdx.x, lane = t & 31, wid = t >> 5;
    const int idx = blockIdx.x * 1024 + t;
    int v = (idx < NSEG) ? g_cnt[idx] : 0;
    int s = v;
#pragma unroll
    for (int off = 1; off < 32; off <<= 1) {
        int n = __shfl_up_sync(0xffffffffu, s, off);
        if (lane >= off) s += n;
    }
    if (lane == 31) wsum[wid] = s;
    __syncthreads();
    if (wid == 0) {
        int w = wsum[lane];
#pragma unroll
        for (int off = 1; off < 32; off <<= 1) {
            int n = __shfl_up_sync(0xffffffffu, w, off);
            if (lane >= off) w += n;
        }
        wsum[lane] = w;
    }
    __syncthreads();
    int incl = s + ((wid > 0) ? wsum[wid - 1] : 0);
    if (idx < NSEG) g_off[idx] = incl - v;       // local exclusive
    if (t == 1023) g_bsum[blockIdx.x] = incl;    // block total
}

// ---------------------------------------------------------------------------
// Kernel 3b: apply block offsets (each block re-scans the 20 block sums)
// ---------------------------------------------------------------------------
__global__ void scanC_kernel() {
    __shared__ int s_pre[NSCANB + 1];
    const int t = threadIdx.x;
    if (t < 32) {
        int v = (t < NSCANB) ? g_bsum[t] : 0;
        int s = v;
#pragma unroll
        for (int off = 1; off < 32; off <<= 1) {
            int n = __shfl_up_sync(0xffffffffu, s, off);
            if (t >= off) s += n;
        }
        if (t < NSCANB) s_pre[t] = s - v;       // exclusive
        if (t == 31)    s_pre[NSCANB] = s;      // grand total
    }
    __syncthreads();
    int idx = blockIdx.x * blockDim.x + t;
    if (idx < NSEG) {
        int o = g_off[idx] + s_pre[idx >> 10];
        g_off[idx] = o;
        g_pos[idx] = o;
    }
    if (idx == 0) g_off[NSEG] = s_pre[NSCANB];
}

// ---------------------------------------------------------------------------
// Kernel 4: edge MLP (f32x2 packed) -> logits, exp, softmax denominators.
// 256 threads, 256 edges/block (1/thread), j-tile 32. smem ~103KB -> 2
// blocks/SM = 16 warps/SM (2x the previous 8), register file is not a
// constraint (128 regs/thread allowed at this occupancy).
// ---------------------------------------------------------------------------
#define EPB 256
#define EA_STRIDE 68
#define MLP_SMEM_FLOATS (8464 + EPB * EA_STRIDE)
#define MLP_SMEM_BYTES  (MLP_SMEM_FLOATS * 4)

extern __shared__ float smem[];

__global__ void __launch_bounds__(256, 2)
mlp_kernel(const float* __restrict__ edge_attr,
           const float* __restrict__ W1,
           const float* __restrict__ b1,
           const float* __restrict__ W2,
           const float* __restrict__ b2,
           float* __restrict__ logits,
           int write_logits) {
    float* W1s = smem;              // [64][128]
    float* b1s = smem + 8192;       // 128
    float* W2s = smem + 8320;       // 128
    float* b2s = smem + 8448;       // 1 (pad to 8464 for 16B alignment)
    float* eas = smem + 8464;       // [256][68]

    const int t = threadIdx.x;

    for (int i = t; i < 8192; i += 256) W1s[i] = W1[i];
    if (t < 128) { b1s[t] = b1[t]; W2s[t] = W2[t]; }
    if (t == 0)  b2s[0] = b2[0];

    const float4* ea4 = reinterpret_cast<const float4*>(
        edge_attr + (size_t)blockIdx.x * EPB * DE);
    for (int i = t; i < EPB * DE / 4; i += 256) {
        float4 v = ea4[i];
        int edge = i >> 4;
        int k4   = i & 15;
        reinterpret_cast<float4*>(&eas[edge * EA_STRIDE])[k4] = v;
    }
    __syncthreads();

    float logit = b2s[0];
    const float4* ea0 = reinterpret_cast<const float4*>(&eas[t * EA_STRIDE]);

#pragma unroll
    for (int j0 = 0; j0 < HID; j0 += 32) {
        unsigned long long acc[16];
        const unsigned long long* b1p =
            reinterpret_cast<const unsigned long long*>(&b1s[j0]);
#pragma unroll
        for (int m = 0; m < 16; m++) acc[m] = b1p[m];

#pragma unroll 4
        for (int k4 = 0; k4 < 16; k4++) {
            float4 a0 = ea0[k4];          // LDS.128, conflict-free
            float a0v[4] = {a0.x, a0.y, a0.z, a0.w};
#pragma unroll
            for (int kk = 0; kk < 4; kk++) {
                unsigned long long A0 = pack2(a0v[kk]);
                const ulonglong2* w2 = reinterpret_cast<const ulonglong2*>(
                    &W1s[(k4 * 4 + kk) * HID + j0]);
#pragma unroll
                for (int m = 0; m < 8; m++) {
                    ulonglong2 w = w2[m];   // broadcast LDS.128
                    acc[2*m]   = ffma2(A0, w.x, acc[2*m]);
                    acc[2*m+1] = ffma2(A0, w.y, acc[2*m+1]);
                }
            }
        }
#pragma unroll
        for (int m = 0; m < 16; m++) {
            U64F2 c0; c0.u = acc[m];
            logit += fmaxf(c0.f.x, 0.f) * W2s[j0 + 2*m]
                   + fmaxf(c0.f.y, 0.f) * W2s[j0 + 2*m + 1];
        }
    }

    const int e0 = blockIdx.x * EPB + t;
    if (write_logits) logits[e0] = logit;
    float ex = expf(logit);
    g_exp[e0] = ex;
    int r = g_row[e0], c = g_col[e0];
    if (r < c)      atomicAdd(&g_sum_out[r], ex);
    else if (r > c) atomicAdd(&g_sum_in[r],  ex);
}

// ---------------------------------------------------------------------------
// Kernel 5: fill CSR lists with final softmax weights (sums ready post-MLP)
// ---------------------------------------------------------------------------
__global__ void fill_kernel() {
    int e = blockIdx.x * blockDim.x + threadIdx.x;
    if (e >= EE) return;
    int r = g_row[e], c = g_col[e];
    if (r == c) return;
    int dirin = (r > c);
    int seg = r * 2 + dirin;
    int pos = atomicAdd(&g_pos[seg], 1);
    float sum = dirin ? g_sum_in[r] : g_sum_out[r];
    g_scol[pos] = c;
    g_sw[pos]   = g_exp[e] / fmaxf(sum, 1e-30f);
}

// ---------------------------------------------------------------------------
// Kernel 6: fused gather-aggregate + 1x1 conv. One block per node.
// ---------------------------------------------------------------------------
#define ECHUNK 128

__global__ void __launch_bounds__(256)
fused_kernel(const float* __restrict__ x,
             const float* __restrict__ Wn,
             const float* __restrict__ bn,
             float* __restrict__ out) {
    __shared__ float s_fo[CHW];      // flow_out
    __shared__ float s_fi[CHW];      // flow_in
    __shared__ float WsT[48 * 16];   // WsT[cc][o] = Wn[o*48+cc]
    __shared__ float bs[16];
    __shared__ int   s_ec[ECHUNK];
    __shared__ float s_ew[ECHUNK];

    const int n = blockIdx.x;
    const int t = threadIdx.x;

    for (int i = t; i < 768; i += 256) {
        int o = i / 48, cc = i % 48;
        WsT[cc * 16 + o] = Wn[i];
    }
    if (t < 16) bs[t] = bn[t];

    const int off0 = g_off[2 * n];
    const int off1 = g_off[2 * n + 1];
    const int off2 = g_off[2 * n + 2];

    const float4* x4 = reinterpret_cast<const float4*>(x);

    float4 accO = make_float4(0.f, 0.f, 0.f, 0.f);
    float4 accI = make_float4(0.f, 0.f, 0.f, 0.f);

    // dir 0: outgoing flow (r < c)
    for (int base = off0; base < off1; base += ECHUNK) {
        int m = min(ECHUNK, off1 - base);
        __syncthreads();
        for (int j = t; j < m; j += 256) {
            s_ec[j] = g_scol[base + j];
            s_ew[j] = g_sw[base + j];
        }
        __syncthreads();
#pragma unroll 4
        for (int j = 0; j < m; j++) {
            float w = s_ew[j];
            float4 xv = __ldg(&x4[(size_t)s_ec[j] * 256 + t]);
            accO.x += w * xv.x; accO.y += w * xv.y;
            accO.z += w * xv.z; accO.w += w * xv.w;
        }
    }
    // dir 1: incoming flow (r > c)
    for (int base = off1; base < off2; base += ECHUNK) {
        int m = min(ECHUNK, off2 - base);
        __syncthreads();
        for (int j = t; j < m; j += 256) {
            s_ec[j] = g_scol[base + j];
            s_ew[j] = g_sw[base + j];
        }
        __syncthreads();
#pragma unroll 4
        for (int j = 0; j < m; j++) {
            float w = s_ew[j];
            float4 xv = __ldg(&x4[(size_t)s_ec[j] * 256 + t]);
            accI.x += w * xv.x; accI.y += w * xv.y;
            accI.z += w * xv.z; accI.w += w * xv.w;
        }
    }

    __syncthreads();
    reinterpret_cast<float4*>(s_fo)[t] = accO;
    reinterpret_cast<float4*>(s_fi)[t] = accI;
    __syncthreads();

    const int hw = t & 63;
    const int og = t >> 6;

    float acc[4];
#pragma unroll
    for (int j = 0; j < 4; j++) acc[j] = bs[og * 4 + j];

    const float* xb = x + (size_t)n * CHW;
#pragma unroll 4
    for (int cc = 0; cc < 16; cc++) {
        float vx = __ldg(&xb[cc * 64 + hw]);
        float vi = s_fi[cc * 64 + hw];
        float vo = s_fo[cc * 64 + hw];
        float4 wx = reinterpret_cast<const float4*>(&WsT[(cc)      * 16])[og];
        float4 wi = reinterpret_cast<const float4*>(&WsT[(16 + cc) * 16])[og];
        float4 wo = reinterpret_cast<const float4*>(&WsT[(32 + cc) * 16])[og];
        acc[0] += vx * wx.x + vi * wi.x + vo * wo.x;
        acc[1] += vx * wx.y + vi * wi.y + vo * wo.y;
        acc[2] += vx * wx.z + vi * wi.z + vo * wo.z;
        acc[3] += vx * wx.w + vi * wi.w + vo * wo.w;
    }

    float* ob = out + (size_t)n * CHW;
#pragma unroll
    for (int j = 0; j < 4; j++)
        ob[(og * 4 + j) * 64 + hw] = acc[j];
}

// ---------------------------------------------------------------------------
// Launch (default stream; sequentially ordered; graph-capturable)
// MLP stays the 4th launch so ncu samples it again (verify occupancy fix).
// ---------------------------------------------------------------------------
extern "C" void kernel_launch(void* const* d_in, const int* in_sizes, int n_in,
                              void* d_out, int out_size) {
    const float* x         = (const float*)d_in[0];
    const float* edge_attr = (const float*)d_in[1];
    const float* W1        = (const float*)d_in[2];
    const float* b1        = (const float*)d_in[3];
    const float* W2        = (const float*)d_in[4];
    const float* b2        = (const float*)d_in[5];
    const float* Wn        = (const float*)d_in[6];
    const float* bn        = (const float*)d_in[7];
    const int*   ei32      = (const int*)d_in[8];

    float* out    = (float*)d_out;
    const int write_logits = (out_size >= NN * CHW + EE);
    float* logits = out + (size_t)NN * CHW;

    cudaFuncSetAttribute(mlp_kernel,
                         cudaFuncAttributeMaxDynamicSharedMemorySize,
                         MLP_SMEM_BYTES);

    const int EB = (EE + 255) / 256;

    zero_kernel<<<(NSEG + 255) / 256, 256>>>(ei32);
    decode_kernel<<<EB, 256>>>(ei32);
    scanA_kernel<<<NSCANB, 1024>>>();
    mlp_kernel<<<EE / EPB, 256, MLP_SMEM_BYTES>>>(edge_attr, W1, b1, W2, b2,
                                                  logits, write_logits);
    scanC_kernel<<<(NSEG + 255) / 256, 256>>>();
    fill_kernel<<<EB, 256>>>();
    fused_kernel<<<NN, 256>>>(x, Wn, bn, out);
}

// round 8
// speedup vs baseline: 1.1493x; 1.1493x over previous
#include <cuda_runtime.h>
#include <cuda_fp16.h>
#include <math.h>

// Problem constants (fixed by the reference)
#define NN    10000
#define EE    160000
#define CC    16
#define CHW   1024       // C*H*W
#define DE    64         // edge feature dim
#define HID   128        // hidden dim
#define NSEG  (2 * NN)   // (node, dir) segments; dir 0 = out (r<c), 1 = in (r>c)
#define NSCANB ((NSEG + 1023) / 1024)   // 20 scan blocks

// ---------------------------------------------------------------------------
// Scratch (__device__ globals; no allocations allowed)
// ---------------------------------------------------------------------------
__device__ float g_sum_in [NN];
__device__ float g_sum_out[NN];
__device__ float g_exp[EE];
__device__ int   g_row[EE];
__device__ int   g_col[EE];
__device__ int   g_is64;
__device__ int   g_cnt[NSEG];
__device__ int   g_off[NSEG + 1];
__device__ int   g_pos[NSEG];
__device__ int   g_bsum[NSCANB];
__device__ int   g_scol[EE];       // col of sorted edge
__device__ float g_sw  [EE];       // softmax weight of sorted edge

// ---------------------------------------------------------------------------
// f32x2 packed helpers (sm_100+): 2 fp32 FMAs per issue slot.
// ---------------------------------------------------------------------------
__device__ __forceinline__ unsigned long long ffma2(unsigned long long a,
                                                    unsigned long long b,
                                                    unsigned long long c) {
    unsigned long long d;
    asm("fma.rn.f32x2 %0, %1, %2, %3;" : "=l"(d) : "l"(a), "l"(b), "l"(c));
    return d;
}
__device__ __forceinline__ unsigned long long pack2(float a) {
    unsigned long long r;
    unsigned int u = __float_as_uint(a);
    asm("mov.b64 %0, {%1, %1};" : "=l"(r) : "r"(u));
    return r;
}
union U64F2 { unsigned long long u; float2 f; };

// ---------------------------------------------------------------------------
// Kernel 1: zero accumulators + (block 0) detect int64 vs int32 edge_index.
// ---------------------------------------------------------------------------
__global__ void zero_kernel(const int* __restrict__ v32) {
    int i = blockIdx.x * blockDim.x + threadIdx.x;
    if (i < NSEG) g_cnt[i] = 0;
    if (i < NN) { g_sum_in[i] = 0.f; g_sum_out[i] = 0.f; }
    if (blockIdx.x == 0 && threadIdx.x < 32) {
        int t = threadIdx.x;
        int nz = 0;
#pragma unroll
        for (int q = 0; q < 4; q++)
            nz |= (v32[2 * (t + q * 32) + 1] != 0);
#pragma unroll
        for (int s = 16; s > 0; s >>= 1)
            nz |= __shfl_xor_sync(0xffffffffu, nz, s);
        if (t == 0) g_is64 = nz ? 0 : 1;
    }
}

// ---------------------------------------------------------------------------
// Kernel 2: decode edge_index + segment histogram (merged)
// ---------------------------------------------------------------------------
__global__ void decode_kernel(const int* __restrict__ v32) {
    int e = blockIdx.x * blockDim.x + threadIdx.x;
    if (e >= EE) return;
    int r, c;
    if (g_is64) { r = v32[2 * e]; c = v32[2 * (EE + e)]; }
    else        { r = v32[e];     c = v32[EE + e]; }
    g_row[e] = r;
    g_col[e] = c;
    if (r != c) atomicAdd(&g_cnt[r * 2 + ((r < c) ? 0 : 1)], 1);
}

// ---------------------------------------------------------------------------
// Kernel 3a: per-block local scan + block sums
// ---------------------------------------------------------------------------
__global__ void scanA_kernel() {      // NSCANB blocks x 1024
    __shared__ int wsum[32];
    const int t = threadIdx.x, lane = t & 31, wid = t >> 5;
    const int idx = blockIdx.x * 1024 + t;
    int v = (idx < NSEG) ? g_cnt[idx] : 0;
    int s = v;
#pragma unroll
    for (int off = 1; off < 32; off <<= 1) {
        int n = __shfl_up_sync(0xffffffffu, s, off);
        if (lane >= off) s += n;
    }
    if (lane == 31) wsum[wid] = s;
    __syncthreads();
    if (wid == 0) {
        int w = wsum[lane];
#pragma unroll
        for (int off = 1; off < 32; off <<= 1) {
            int n = __shfl_up_sync(0xffffffffu, w, off);
            if (lane >= off) w += n;
        }
        wsum[lane] = w;
    }
    __syncthreads();
    int incl = s + ((wid > 0) ? wsum[wid - 1] : 0);
    if (idx < NSEG) g_off[idx] = incl - v;       // local exclusive
    if (t == 1023) g_bsum[blockIdx.x] = incl;    // block total
}

// ---------------------------------------------------------------------------
// Kernel 3b: apply block offsets (each block re-scans the 20 block sums)
// ---------------------------------------------------------------------------
__global__ void scanC_kernel() {
    __shared__ int s_pre[NSCANB + 1];
    const int t = threadIdx.x;
    if (t < 32) {
        int v = (t < NSCANB) ? g_bsum[t] : 0;
        int s = v;
#pragma unroll
        for (int off = 1; off < 32; off <<= 1) {
            int n = __shfl_up_sync(0xffffffffu, s, off);
            if (t >= off) s += n;
        }
        if (t < NSCANB) s_pre[t] = s - v;       // exclusive
        if (t == 31)    s_pre[NSCANB] = s;      // grand total
    }
    __syncthreads();
    int idx = blockIdx.x * blockDim.x + t;
    if (idx < NSEG) {
        int o = g_off[idx] + s_pre[idx >> 10];
        g_off[idx] = o;
        g_pos[idx] = o;
    }
    if (idx == 0) g_off[NSEG] = s_pre[NSCANB];
}

// ---------------------------------------------------------------------------
// Kernel 4: edge MLP (f32x2 packed) -> logits, exp, softmax denominators.
// 256 threads, 512 edges/block (2/thread): edge_attr staged as FP16 in smem
// (the only rounded quantity; W1/accumulation stay fp32). smem ~107.6KB ->
// 2 blocks/SM = 16 warps/SM *with* 2-edge W1-LDS amortization (FFMA2:LDS=4:1).
// ---------------------------------------------------------------------------
#define EPB 512
#define EA_STRIDE_H 72      // halfs per edge row (144B, conflict-free LDS.128)
#define MLP_SMEM_BYTES (8464 * 4 + EPB * EA_STRIDE_H * 2)

extern __shared__ float smem[];

__global__ void __launch_bounds__(256, 2)
mlp_kernel(const float* __restrict__ edge_attr,
           const float* __restrict__ W1,
           const float* __restrict__ b1,
           const float* __restrict__ W2,
           const float* __restrict__ b2,
           float* __restrict__ logits,
           int write_logits) {
    float* W1s = smem;              // [64][128]
    float* b1s = smem + 8192;       // 128
    float* W2s = smem + 8320;       // 128
    float* b2s = smem + 8448;       // 1 (pad region to 8464 for 16B alignment)
    __half* eas = reinterpret_cast<__half*>(smem + 8464);  // [512][72] halfs

    const int t = threadIdx.x;

    for (int i = t; i < 8192; i += 256) W1s[i] = W1[i];
    if (t < 128) { b1s[t] = b1[t]; W2s[t] = W2[t]; }
    if (t == 0)  b2s[0] = b2[0];

    // Stage 512 edges of edge_attr as fp16 (guarded: last block is partial)
    const float4* ea4 = reinterpret_cast<const float4*>(edge_attr);
    const int gbase = blockIdx.x * (EPB * DE / 4);
    for (int i = t; i < EPB * DE / 4; i += 256) {
        int gi = gbase + i;
        float4 v = (gi < EE * DE / 4) ? ea4[gi]
                                      : make_float4(0.f, 0.f, 0.f, 0.f);
        int ed = i >> 4;            // 16 float4 per edge
        int k4 = i & 15;
        __half2 h01 = __floats2half2_rn(v.x, v.y);
        __half2 h23 = __floats2half2_rn(v.z, v.w);
        uint2 pk;
        pk.x = *reinterpret_cast<unsigned*>(&h01);
        pk.y = *reinterpret_cast<unsigned*>(&h23);
        *reinterpret_cast<uint2*>(eas + ed * EA_STRIDE_H + k4 * 4) = pk;
    }
    __syncthreads();

    float logit0 = b2s[0];
    float logit1 = b2s[0];
    const uint4* eaA = reinterpret_cast<const uint4*>(eas + t * EA_STRIDE_H);
    const uint4* eaB = reinterpret_cast<const uint4*>(
        eas + (t + 256) * EA_STRIDE_H);

#pragma unroll 1
    for (int j0 = 0; j0 < HID; j0 += 32) {
        unsigned long long acc0[16], acc1[16];
        const unsigned long long* b1p =
            reinterpret_cast<const unsigned long long*>(&b1s[j0]);
#pragma unroll
        for (int m = 0; m < 16; m++) { acc0[m] = b1p[m]; acc1[m] = b1p[m]; }

#pragma unroll 2
        for (int k8 = 0; k8 < 8; k8++) {      // 8 halfs per uint4 load
            uint4 ra = eaA[k8];               // LDS.128, conflict-free
            uint4 rb = eaB[k8];
            unsigned va[4] = {ra.x, ra.y, ra.z, ra.w};
            unsigned vb[4] = {rb.x, rb.y, rb.z, rb.w};
#pragma unroll
            for (int q = 0; q < 4; q++) {
                __half2 ha = *reinterpret_cast<__half2*>(&va[q]);
                __half2 hb = *reinterpret_cast<__half2*>(&vb[q]);
                float2 fa = __half22float2(ha);
                float2 fb = __half22float2(hb);
                const int kb = k8 * 8 + q * 2;
#pragma unroll
                for (int kk = 0; kk < 2; kk++) {
                    unsigned long long A0 = pack2(kk ? fa.y : fa.x);
                    unsigned long long A1 = pack2(kk ? fb.y : fb.x);
                    const ulonglong2* w2 =
                        reinterpret_cast<const ulonglong2*>(
                            &W1s[(kb + kk) * HID + j0]);
#pragma unroll
                    for (int m = 0; m < 8; m++) {
                        ulonglong2 w = w2[m];   // broadcast LDS.128
                        acc0[2*m]   = ffma2(A0, w.x, acc0[2*m]);
                        acc0[2*m+1] = ffma2(A0, w.y, acc0[2*m+1]);
                        acc1[2*m]   = ffma2(A1, w.x, acc1[2*m]);
                        acc1[2*m+1] = ffma2(A1, w.y, acc1[2*m+1]);
                    }
                }
            }
        }
#pragma unroll
        for (int m = 0; m < 16; m++) {
            U64F2 c0; c0.u = acc0[m];
            U64F2 c1; c1.u = acc1[m];
            float w2a = W2s[j0 + 2*m];
            float w2b = W2s[j0 + 2*m + 1];
            logit0 += fmaxf(c0.f.x, 0.f) * w2a + fmaxf(c0.f.y, 0.f) * w2b;
            logit1 += fmaxf(c1.f.x, 0.f) * w2a + fmaxf(c1.f.y, 0.f) * w2b;
        }
    }

    const int e0 = blockIdx.x * EPB + t;
    const int e1 = e0 + 256;
    if (e0 < EE) {
        if (write_logits) logits[e0] = logit0;
        float ex = expf(logit0);
        g_exp[e0] = ex;
        int r = g_row[e0], c = g_col[e0];
        if (r < c)      atomicAdd(&g_sum_out[r], ex);
        else if (r > c) atomicAdd(&g_sum_in[r],  ex);
    }
    if (e1 < EE) {
        if (write_logits) logits[e1] = logit1;
        float ex = expf(logit1);
        g_exp[e1] = ex;
        int r = g_row[e1], c = g_col[e1];
        if (r < c)      atomicAdd(&g_sum_out[r], ex);
        else if (r > c) atomicAdd(&g_sum_in[r],  ex);
    }
}

// ---------------------------------------------------------------------------
// Kernel 5: fill CSR lists with final softmax weights (sums ready post-MLP)
// ---------------------------------------------------------------------------
__global__ void fill_kernel() {
    int e = blockIdx.x * blockDim.x + threadIdx.x;
    if (e >= EE) return;
    int r = g_row[e], c = g_col[e];
    if (r == c) return;
    int dirin = (r > c);
    int seg = r * 2 + dirin;
    int pos = atomicAdd(&g_pos[seg], 1);
    float sum = dirin ? g_sum_in[r] : g_sum_out[r];
    g_scol[pos] = c;
    g_sw[pos]   = g_exp[e] / fmaxf(sum, 1e-30f);
}

// ---------------------------------------------------------------------------
// Kernel 6: fused gather-aggregate + 1x1 conv. One block per node.
// ---------------------------------------------------------------------------
#define ECHUNK 128

__global__ void __launch_bounds__(256)
fused_kernel(const float* __restrict__ x,
             const float* __restrict__ Wn,
             const float* __restrict__ bn,
             float* __restrict__ out) {
    __shared__ float s_fo[CHW];      // flow_out
    __shared__ float s_fi[CHW];      // flow_in
    __shared__ float WsT[48 * 16];   // WsT[cc][o] = Wn[o*48+cc]
    __shared__ float bs[16];
    __shared__ int   s_ec[ECHUNK];
    __shared__ float s_ew[ECHUNK];

    const int n = blockIdx.x;
    const int t = threadIdx.x;

    for (int i = t; i < 768; i += 256) {
        int o = i / 48, cc = i % 48;
        WsT[cc * 16 + o] = Wn[i];
    }
    if (t < 16) bs[t] = bn[t];

    const int off0 = g_off[2 * n];
    const int off1 = g_off[2 * n + 1];
    const int off2 = g_off[2 * n + 2];

    const float4* x4 = reinterpret_cast<const float4*>(x);

    float4 accO = make_float4(0.f, 0.f, 0.f, 0.f);
    float4 accI = make_float4(0.f, 0.f, 0.f, 0.f);

    // dir 0: outgoing flow (r < c)
    for (int base = off0; base < off1; base += ECHUNK) {
        int m = min(ECHUNK, off1 - base);
        __syncthreads();
        for (int j = t; j < m; j += 256) {
            s_ec[j] = g_scol[base + j];
            s_ew[j] = g_sw[base + j];
        }
        __syncthreads();
#pragma unroll 4
        for (int j = 0; j < m; j++) {
            float w = s_ew[j];
            float4 xv = __ldg(&x4[(size_t)s_ec[j] * 256 + t]);
            accO.x += w * xv.x; accO.y += w * xv.y;
            accO.z += w * xv.z; accO.w += w * xv.w;
        }
    }
    // dir 1: incoming flow (r > c)
    for (int base = off1; base < off2; base += ECHUNK) {
        int m = min(ECHUNK, off2 - base);
        __syncthreads();
        for (int j = t; j < m; j += 256) {
            s_ec[j] = g_scol[base + j];
            s_ew[j] = g_sw[base + j];
        }
        __syncthreads();
#pragma unroll 4
        for (int j = 0; j < m; j++) {
            float w = s_ew[j];
            float4 xv = __ldg(&x4[(size_t)s_ec[j] * 256 + t]);
            accI.x += w * xv.x; accI.y += w * xv.y;
            accI.z += w * xv.z; accI.w += w * xv.w;
        }
    }

    __syncthreads();
    reinterpret_cast<float4*>(s_fo)[t] = accO;
    reinterpret_cast<float4*>(s_fi)[t] = accI;
    __syncthreads();

    const int hw = t & 63;
    const int og = t >> 6;

    float acc[4];
#pragma unroll
    for (int j = 0; j < 4; j++) acc[j] = bs[og * 4 + j];

    const float* xb = x + (size_t)n * CHW;
#pragma unroll 4
    for (int cc = 0; cc < 16; cc++) {
        float vx = __ldg(&xb[cc * 64 + hw]);
        float vi = s_fi[cc * 64 + hw];
        float vo = s_fo[cc * 64 + hw];
        float4 wx = reinterpret_cast<const float4*>(&WsT[(cc)      * 16])[og];
        float4 wi = reinterpret_cast<const float4*>(&WsT[(16 + cc) * 16])[og];
        float4 wo = reinterpret_cast<const float4*>(&WsT[(32 + cc) * 16])[og];
        acc[0] += vx * wx.x + vi * wi.x + vo * wo.x;
        acc[1] += vx * wx.y + vi * wi.y + vo * wo.y;
        acc[2] += vx * wx.z + vi * wi.z + vo * wo.z;
        acc[3] += vx * wx.w + vi * wi.w + vo * wo.w;
    }

    float* ob = out + (size_t)n * CHW;
#pragma unroll
    for (int j = 0; j < 4; j++)
        ob[(og * 4 + j) * 64 + hw] = acc[j];
}

// ---------------------------------------------------------------------------
// Launch (default stream; sequentially ordered; graph-capturable)
// MLP stays the 4th launch so ncu samples it (verify fma/L1 balance).
// ---------------------------------------------------------------------------
extern "C" void kernel_launch(void* const* d_in, const int* in_sizes, int n_in,
                              void* d_out, int out_size) {
    const float* x         = (const float*)d_in[0];
    const float* edge_attr = (const float*)d_in[1];
    const float* W1        = (const float*)d_in[2];
    const float* b1        = (const float*)d_in[3];
    const float* W2        = (const float*)d_in[4];
    const float* b2        = (const float*)d_in[5];
    const float* Wn        = (const float*)d_in[6];
    const float* bn        = (const float*)d_in[7];
    const int*   ei32      = (const int*)d_in[8];

    float* out    = (float*)d_out;
    const int write_logits = (out_size >= NN * CHW + EE);
    float* logits = out + (size_t)NN * CHW;

    cudaFuncSetAttribute(mlp_kernel,
                         cudaFuncAttributeMaxDynamicSharedMemorySize,
                         MLP_SMEM_BYTES);

    const int EB = (EE + 255) / 256;

    zero_kernel<<<(NSEG + 255) / 256, 256>>>(ei32);
    decode_kernel<<<EB, 256>>>(ei32);
    scanA_kernel<<<NSCANB, 1024>>>();
    mlp_kernel<<<(EE + EPB - 1) / EPB, 256, MLP_SMEM_BYTES>>>(
        edge_attr, W1, b1, W2, b2, logits, write_logits);
    scanC_kernel<<<(NSEG + 255) / 256, 256>>>();
    fill_kernel<<<EB, 256>>>();
    fused_kernel<<<NN, 256>>>(x, Wn, bn, out);
}

// round 10
// speedup vs baseline: 1.4490x; 1.2608x over previous
#include <cuda_runtime.h>
#include <cuda_fp16.h>
#include <cstdint>
#include <math.h>

// Problem constants (fixed by the reference)
#define NN    10000
#define EE    160000
#define CC    16
#define CHW   1024       // C*H*W
#define DE    64         // edge feature dim
#define HID   128        // hidden dim
#define NSEG  (2 * NN)   // (node, dir) segments; dir 0 = out (r<c), 1 = in (r>c)
#define NSCANB ((NSEG + 1023) / 1024)   // 20 scan blocks

// ---------------------------------------------------------------------------
// Scratch (__device__ globals; no allocations allowed)
// ---------------------------------------------------------------------------
__device__ float g_sum_in [NN];
__device__ float g_sum_out[NN];
__device__ float g_exp[EE];
__device__ int   g_row[EE];
__device__ int   g_col[EE];
__device__ int   g_is64;
__device__ int   g_cnt[NSEG];
__device__ int   g_off[NSEG + 1];
__device__ int   g_pos[NSEG];
__device__ int   g_bsum[NSCANB];
__device__ int   g_scol[EE];       // col of sorted edge
__device__ float g_sw  [EE];       // softmax weight of sorted edge

// ---------------------------------------------------------------------------
// Kernel 1: zero accumulators + (block 0) detect int64 vs int32 edge_index.
// ---------------------------------------------------------------------------
__global__ void zero_kernel(const int* __restrict__ v32) {
    int i = blockIdx.x * blockDim.x + threadIdx.x;
    if (i < NSEG) g_cnt[i] = 0;
    if (i < NN) { g_sum_in[i] = 0.f; g_sum_out[i] = 0.f; }
    if (blockIdx.x == 0 && threadIdx.x < 32) {
        int t = threadIdx.x;
        int nz = 0;
#pragma unroll
        for (int q = 0; q < 4; q++)
            nz |= (v32[2 * (t + q * 32) + 1] != 0);
#pragma unroll
        for (int s = 16; s > 0; s >>= 1)
            nz |= __shfl_xor_sync(0xffffffffu, nz, s);
        if (t == 0) g_is64 = nz ? 0 : 1;
    }
}

// ---------------------------------------------------------------------------
// Kernel 2: decode edge_index + segment histogram (merged)
// ---------------------------------------------------------------------------
__global__ void decode_kernel(const int* __restrict__ v32) {
    int e = blockIdx.x * blockDim.x + threadIdx.x;
    if (e >= EE) return;
    int r, c;
    if (g_is64) { r = v32[2 * e]; c = v32[2 * (EE + e)]; }
    else        { r = v32[e];     c = v32[EE + e]; }
    g_row[e] = r;
    g_col[e] = c;
    if (r != c) atomicAdd(&g_cnt[r * 2 + ((r < c) ? 0 : 1)], 1);
}

// ---------------------------------------------------------------------------
// Kernel 3a: per-block local scan + block sums
// ---------------------------------------------------------------------------
__global__ void scanA_kernel() {      // NSCANB blocks x 1024
    __shared__ int wsum[32];
    const int t = threadIdx.x, lane = t & 31, wid = t >> 5;
    const int idx = blockIdx.x * 1024 + t;
    int v = (idx < NSEG) ? g_cnt[idx] : 0;
    int s = v;
#pragma unroll
    for (int off = 1; off < 32; off <<= 1) {
        int n = __shfl_up_sync(0xffffffffu, s, off);
        if (lane >= off) s += n;
    }
    if (lane == 31) wsum[wid] = s;
    __syncthreads();
    if (wid == 0) {
        int w = wsum[lane];
#pragma unroll
        for (int off = 1; off < 32; off <<= 1) {
            int n = __shfl_up_sync(0xffffffffu, w, off);
            if (lane >= off) w += n;
        }
        wsum[lane] = w;
    }
    __syncthreads();
    int incl = s + ((wid > 0) ? wsum[wid - 1] : 0);
    if (idx < NSEG) g_off[idx] = incl - v;       // local exclusive
    if (t == 1023) g_bsum[blockIdx.x] = incl;    // block total
}

// ---------------------------------------------------------------------------
// Kernel 3b: apply block offsets (each block re-scans the 20 block sums)
// ---------------------------------------------------------------------------
__global__ void scanC_kernel() {
    __shared__ int s_pre[NSCANB + 1];
    const int t = threadIdx.x;
    if (t < 32) {
        int v = (t < NSCANB) ? g_bsum[t] : 0;
        int s = v;
#pragma unroll
        for (int off = 1; off < 32; off <<= 1) {
            int n = __shfl_up_sync(0xffffffffu, s, off);
            if (t >= off) s += n;
        }
        if (t < NSCANB) s_pre[t] = s - v;       // exclusive
        if (t == 31)    s_pre[NSCANB] = s;      // grand total
    }
    __syncthreads();
    int idx = blockIdx.x * blockDim.x + t;
    if (idx < NSEG) {
        int o = g_off[idx] + s_pre[idx >> 10];
        g_off[idx] = o;
        g_pos[idx] = o;
    }
    if (idx == 0) g_off[NSEG] = s_pre[NSCANB];
}

// ---------------------------------------------------------------------------
// Kernel 4: edge MLP on the TENSOR pipe (mma.m16n8k16 f16->f32).
// 256 threads = 8 warps x 32 edges (2 A-tiles of m16). Grid 625 (exact).
// edge_attr + W1 staged fp16 (stride-72 rows -> conflict-free ldmatrix/LDS);
// accumulation fp32; per-ntile epilogue fuses b1+relu+W2 dot.
// ---------------------------------------------------------------------------
#define EPB 256
#define EAS 72                      // half stride per row (144B)
#define SM_W1T  0                   // [128][72] halfs = 18432 B
#define SM_EAS  18432               // [256][72] halfs = 36864 B
#define SM_B1   55296               // 128 floats
#define SM_W2   55808               // 128 floats
#define SM_B2   56320               // 1 float
#define MLP_SMEM_BYTES 56448

__device__ __forceinline__ unsigned smem_u32(const void* p) {
    return (unsigned)__cvta_generic_to_shared(p);
}

__global__ void __launch_bounds__(256, 2)
mlp_kernel(const float* __restrict__ edge_attr,
           const float* __restrict__ W1,
           const float* __restrict__ b1,
           const float* __restrict__ W2,
           const float* __restrict__ b2,
           float* __restrict__ logits,
           int write_logits) {
    extern __shared__ char smemraw[];
    __half* W1T = reinterpret_cast<__half*>(smemraw + SM_W1T);
    __half* eas = reinterpret_cast<__half*>(smemraw + SM_EAS);
    float*  b1s = reinterpret_cast<float*>(smemraw + SM_B1);
    float*  W2s = reinterpret_cast<float*>(smemraw + SM_W2);
    float*  b2s = reinterpret_cast<float*>(smemraw + SM_B2);

    const int t = threadIdx.x;

    // Stage W1 transposed as fp16: W1T[n][k] = W1[k][n]
    for (int i = t; i < DE * HID; i += 256) {
        int k = i >> 7, n = i & 127;
        W1T[n * EAS + k] = __float2half_rn(W1[i]);
    }
    if (t < 128) { b1s[t] = b1[t]; W2s[t] = W2[t]; }
    if (t == 0)  b2s[0] = b2[0];

    // Stage 256 edges of edge_attr as fp16, stride-72 rows
    const float4* ea4 = reinterpret_cast<const float4*>(
        edge_attr + (size_t)blockIdx.x * EPB * DE);
    for (int i = t; i < EPB * DE / 4; i += 256) {
        float4 v = ea4[i];
        int ed = i >> 4;            // 16 float4 per edge
        int k4 = i & 15;
        __half2 h01 = __floats2half2_rn(v.x, v.y);
        __half2 h23 = __floats2half2_rn(v.z, v.w);
        uint2 pk;
        pk.x = *reinterpret_cast<unsigned*>(&h01);
        pk.y = *reinterpret_cast<unsigned*>(&h23);
        *reinterpret_cast<uint2*>(eas + ed * EAS + k4 * 4) = pk;
    }
    __syncthreads();

    const int wid  = t >> 5;
    const int lane = t & 31;
    const int gid  = lane >> 2;     // 0..7
    const int tig  = lane & 3;      // 0..3
    const int ebase = wid * 32;     // this warp's 32 edges (2 m16-tiles)

    // Load A fragments: [2 tiles][4 k-chunks][4 regs] via ldmatrix.x4
    unsigned afr[2][4][4];
    const int arow  = ebase + (lane & 15);
    const int acolh = (lane >> 4) * 8;
#pragma unroll
    for (int tile = 0; tile < 2; tile++) {
#pragma unroll
        for (int kc = 0; kc < 4; kc++) {
            unsigned addr = smem_u32(
                &eas[(arow + tile * 16) * EAS + kc * 16 + acolh]);
            asm volatile(
                "ldmatrix.sync.aligned.m8n8.x4.shared.b16 {%0,%1,%2,%3}, [%4];"
                : "=r"(afr[tile][kc][0]), "=r"(afr[tile][kc][1]),
                  "=r"(afr[tile][kc][2]), "=r"(afr[tile][kc][3])
                : "r"(addr));
        }
    }

    float lp[4] = {0.f, 0.f, 0.f, 0.f};   // [tile*2 + rowhalf]

#pragma unroll 4
    for (int nt = 0; nt < 16; nt++) {
        // B fragments for this n-tile: conflict-free LDS.32 from W1T
        const __half* wb = &W1T[(nt * 8 + gid) * EAS];
        unsigned bfr[4][2];
#pragma unroll
        for (int kc = 0; kc < 4; kc++) {
            bfr[kc][0] = *reinterpret_cast<const unsigned*>(
                wb + kc * 16 + 2 * tig);
            bfr[kc][1] = *reinterpret_cast<const unsigned*>(
                wb + kc * 16 + 2 * tig + 8);
        }
        const int colb = nt * 8 + tig * 2;
        float b1a = b1s[colb],  b1b = b1s[colb + 1];
        float w2a = W2s[colb],  w2b = W2s[colb + 1];

#pragma unroll
        for (int tile = 0; tile < 2; tile++) {
            float c0 = 0.f, c1 = 0.f, c2 = 0.f, c3 = 0.f;
#pragma unroll
            for (int kc = 0; kc < 4; kc++) {
                asm volatile(
                    "mma.sync.aligned.m16n8k16.row.col.f32.f16.f16.f32 "
                    "{%0,%1,%2,%3}, {%4,%5,%6,%7}, {%8,%9}, {%0,%1,%2,%3};"
                    : "+f"(c0), "+f"(c1), "+f"(c2), "+f"(c3)
                    : "r"(afr[tile][kc][0]), "r"(afr[tile][kc][1]),
                      "r"(afr[tile][kc][2]), "r"(afr[tile][kc][3]),
                      "r"(bfr[kc][0]), "r"(bfr[kc][1]));
            }
            lp[tile*2+0] += fmaxf(c0 + b1a, 0.f) * w2a
                          + fmaxf(c1 + b1b, 0.f) * w2b;
            lp[tile*2+1] += fmaxf(c2 + b1a, 0.f) * w2a
                          + fmaxf(c3 + b1b, 0.f) * w2b;
        }
    }

    // Reduce across the 4-thread quad (tig dimension)
#pragma unroll
    for (int s = 1; s <= 2; s <<= 1) {
#pragma unroll
        for (int m = 0; m < 4; m++)
            lp[m] += __shfl_xor_sync(0xffffffffu, lp[m], s);
    }

    if (tig == 0) {
        float bb = b2s[0];
#pragma unroll
        for (int tile = 0; tile < 2; tile++) {
#pragma unroll
            for (int h = 0; h < 2; h++) {
                int e = blockIdx.x * EPB + ebase + tile * 16 + h * 8 + gid;
                float logit = lp[tile * 2 + h] + bb;
                if (write_logits) logits[e] = logit;
                float ex = expf(logit);
                g_exp[e] = ex;
                int r = g_row[e], c = g_col[e];
                if (r < c)      atomicAdd(&g_sum_out[r], ex);
                else if (r > c) atomicAdd(&g_sum_in[r],  ex);
            }
        }
    }
}

// ---------------------------------------------------------------------------
// Kernel 5: fill CSR lists with final softmax weights (sums ready post-MLP)
// ---------------------------------------------------------------------------
__global__ void fill_kernel() {
    int e = blockIdx.x * blockDim.x + threadIdx.x;
    if (e >= EE) return;
    int r = g_row[e], c = g_col[e];
    if (r == c) return;
    int dirin = (r > c);
    int seg = r * 2 + dirin;
    int pos = atomicAdd(&g_pos[seg], 1);
    float sum = dirin ? g_sum_in[r] : g_sum_out[r];
    g_scol[pos] = c;
    g_sw[pos]   = g_exp[e] / fmaxf(sum, 1e-30f);
}

// ---------------------------------------------------------------------------
// Kernel 6: fused gather-aggregate + 1x1 conv. One block per node.
// ---------------------------------------------------------------------------
#define ECHUNK 128

__global__ void __launch_bounds__(256)
fused_kernel(const float* __restrict__ x,
             const float* __restrict__ Wn,
             const float* __restrict__ bn,
             float* __restrict__ out) {
    __shared__ float s_fo[CHW];      // flow_out
    __shared__ float s_fi[CHW];      // flow_in
    __shared__ float WsT[48 * 16];   // WsT[cc][o] = Wn[o*48+cc]
    __shared__ float bs[16];
    __shared__ int   s_ec[ECHUNK];
    __shared__ float s_ew[ECHUNK];

    const int n = blockIdx.x;
    const int t = threadIdx.x;

    for (int i = t; i < 768; i += 256) {
        int o = i / 48, cc = i % 48;
        WsT[cc * 16 + o] = Wn[i];
    }
    if (t < 16) bs[t] = bn[t];

    const int off0 = g_off[2 * n];
    const int off1 = g_off[2 * n + 1];
    const int off2 = g_off[2 * n + 2];

    const float4* x4 = reinterpret_cast<const float4*>(x);

    float4 accO = make_float4(0.f, 0.f, 0.f, 0.f);
    float4 accI = make_float4(0.f, 0.f, 0.f, 0.f);

    // dir 0: outgoing flow (r < c)
    for (int base = off0; base < off1; base += ECHUNK) {
        int m = min(ECHUNK, off1 - base);
        __syncthreads();
        for (int j = t; j < m; j += 256) {
            s_ec[j] = g_scol[base + j];
            s_ew[j] = g_sw[base + j];
        }
        __syncthreads();
#pragma unroll 4
        for (int j = 0; j < m; j++) {
            float w = s_ew[j];
            float4 xv = __ldg(&x4[(size_t)s_ec[j] * 256 + t]);
            accO.x += w * xv.x; accO.y += w * xv.y;
            accO.z += w * xv.z; accO.w += w * xv.w;
        }
    }
    // dir 1: incoming flow (r > c)
    for (int base = off1; base < off2; base += ECHUNK) {
        int m = min(ECHUNK, off2 - base);
        __syncthreads();
        for (int j = t; j < m; j += 256) {
            s_ec[j] = g_scol[base + j];
            s_ew[j] = g_sw[base + j];
        }
        __syncthreads();
#pragma unroll 4
        for (int j = 0; j < m; j++) {
            float w = s_ew[j];
            float4 xv = __ldg(&x4[(size_t)s_ec[j] * 256 + t]);
            accI.x += w * xv.x; accI.y += w * xv.y;
            accI.z += w * xv.z; accI.w += w * xv.w;
        }
    }

    __syncthreads();
    reinterpret_cast<float4*>(s_fo)[t] = accO;
    reinterpret_cast<float4*>(s_fi)[t] = accI;
    __syncthreads();

    const int hw = t & 63;
    const int og = t >> 6;

    float acc[4];
#pragma unroll
    for (int j = 0; j < 4; j++) acc[j] = bs[og * 4 + j];

    const float* xb = x + (size_t)n * CHW;
#pragma unroll 4
    for (int cc = 0; cc < 16; cc++) {
        float vx = __ldg(&xb[cc * 64 + hw]);
        float vi = s_fi[cc * 64 + hw];
        float vo = s_fo[cc * 64 + hw];
        float4 wx = reinterpret_cast<const float4*>(&WsT[(cc)      * 16])[og];
        float4 wi = reinterpret_cast<const float4*>(&WsT[(16 + cc) * 16])[og];
        float4 wo = reinterpret_cast<const float4*>(&WsT[(32 + cc) * 16])[og];
        acc[0] += vx * wx.x + vi * wi.x + vo * wo.x;
        acc[1] += vx * wx.y + vi * wi.y + vo * wo.y;
        acc[2] += vx * wx.z + vi * wi.z + vo * wo.z;
        acc[3] += vx * wx.w + vi * wi.w + vo * wo.w;
    }

    float* ob = out + (size_t)n * CHW;
#pragma unroll
    for (int j = 0; j < 4; j++)
        ob[(og * 4 + j) * 64 + hw] = acc[j];
}

// ---------------------------------------------------------------------------
// Launch (default stream; sequentially ordered; graph-capturable)
// MLP stays the 4th launch so ncu samples it (verify tensor-pipe switch).
// ---------------------------------------------------------------------------
extern "C" void kernel_launch(void* const* d_in, const int* in_sizes, int n_in,
                              void* d_out, int out_size) {
    const float* x         = (const float*)d_in[0];
    const float* edge_attr = (const float*)d_in[1];
    const float* W1        = (const float*)d_in[2];
    const float* b1        = (const float*)d_in[3];
    const float* W2        = (const float*)d_in[4];
    const float* b2        = (const float*)d_in[5];
    const float* Wn        = (const float*)d_in[6];
    const float* bn        = (const float*)d_in[7];
    const int*   ei32      = (const int*)d_in[8];

    float* out    = (float*)d_out;
    const int write_logits = (out_size >= NN * CHW + EE);
    float* logits = out + (size_t)NN * CHW;

    cudaFuncSetAttribute(mlp_kernel,
                         cudaFuncAttributeMaxDynamicSharedMemorySize,
                         MLP_SMEM_BYTES);

    const int EB = (EE + 255) / 256;

    zero_kernel<<<(NSEG + 255) / 256, 256>>>(ei32);
    decode_kernel<<<EB, 256>>>(ei32);
    scanA_kernel<<<NSCANB, 1024>>>();
    mlp_kernel<<<EE / EPB, 256, MLP_SMEM_BYTES>>>(edge_attr, W1, b1, W2, b2,
                                                  logits, write_logits);
    scanC_kernel<<<(NSEG + 255) / 256, 256>>>();
    fill_kernel<<<EB, 256>>>();
    fused_kernel<<<NN, 256>>>(x, Wn, bn, out);
}